// round 13
// baseline (speedup 1.0000x reference)
#include <cuda_runtime.h>
#include <cstdint>
#include <math.h>

#define BB 8
#define CC 256
#define HH 96
#define WW 128
#define HWSZ (HH*WW)
#define RD 4
#define ND 9

#define HQB 8            // hq rows per CTA (one per warp-pair)
#define WT 16            // w tile
#define NB 24            // B columns (WT + 2*RD)
#define KC 16            // channels per stage
#define NSTG (CC/KC)     // 16
#define APITCH 20
#define BPITCH 20
#define NTHREADS 512

// smem float offsets
#define SA_STG (16*16*APITCH)          // 5120 per buffer
#define SB_OFF (2*SA_STG)              // 10240
#define SB_STG (HQB*NB*BPITCH)         // 3840
#define S_AN   (SB_OFF + 2*SB_STG)     // 17920 : A-norm partials [2][256]
#define S_BN   (S_AN + 512)            // B-norm partials [2][192]
#define S_IVA  (S_BN + 384)            // invA [256]
#define S_IVB  (S_IVA + 256)           // invB [192]
#define SMEM_FLOATS (S_IVB + 192)
#define SMEM_BYTES (SMEM_FLOATS*4)

typedef unsigned int u32;

__device__ __forceinline__ unsigned smem_u32(const void* p) {
    return (unsigned)__cvta_generic_to_shared(p);
}
__device__ __forceinline__ u32 cvt_tf32(float v) {
    u32 r; asm("cvt.rna.tf32.f32 %0, %1;" : "=r"(r) : "f"(v)); return r;
}
__device__ __forceinline__ void mma_tf32(float c[4], const u32 a[4], const u32 b[2]) {
    asm volatile(
        "mma.sync.aligned.m16n8k8.row.col.f32.tf32.tf32.f32 "
        "{%0,%1,%2,%3}, {%4,%5,%6,%7}, {%8,%9}, {%0,%1,%2,%3};"
        : "+f"(c[0]), "+f"(c[1]), "+f"(c[2]), "+f"(c[3])
        : "r"(a[0]), "r"(a[1]), "r"(a[2]), "r"(a[3]), "r"(b[0]), "r"(b[1]));
}
__device__ __forceinline__ void ldm_x4(u32 r[4], unsigned addr) {
    asm volatile("ldmatrix.sync.aligned.m8n8.x4.shared.b16 {%0,%1,%2,%3}, [%4];"
                 : "=r"(r[0]), "=r"(r[1]), "=r"(r[2]), "=r"(r[3]) : "r"(addr));
}
__device__ __forceinline__ void ldm_x2(u32 r[2], unsigned addr) {
    asm volatile("ldmatrix.sync.aligned.m8n8.x2.shared.b16 {%0,%1}, [%2];"
                 : "=r"(r[0]), "=r"(r[1]) : "r"(addr));
}

__global__ __launch_bounds__(NTHREADS, 1)
void corr_mma_kernel(const float* __restrict__ fr, const float* __restrict__ fq,
                     float* __restrict__ out) {
    extern __shared__ float sm[];
    const int tid  = threadIdx.x;
    const int wid  = tid >> 5;
    const int lane = tid & 31;

    const int b   = blockIdx.z;
    const int hq0 = blockIdx.y * HQB;
    const int w0  = blockIdx.x * WT;

    // ---- structural-zero outputs (OOB fq rows): written by edge CTAs
    {
        const int pd[10] = {0,0,0,0,1,1,1,2,2,3};
        const int ph[10] = {0,1,2,3,0,1,2,0,1,0};
        if (blockIdx.y == 0) {
            for (int idx = tid; idx < 1440; idx += NTHREADS) {
                int p = idx / 144, rem = idx % 144, dx = rem / 16, w = rem % 16;
                out[((size_t)b * 81 + pd[p] * ND + dx) * HWSZ + ph[p] * WW + w0 + w] = 0.f;
            }
        }
        if (blockIdx.y == (HH / HQB) - 1) {
            for (int idx = tid; idx < 1440; idx += NTHREADS) {
                int p = idx / 144, rem = idx % 144, dx = rem / 16, w = rem % 16;
                out[((size_t)b * 81 + (8 - pd[p]) * ND + dx) * HWSZ
                    + (HH - 1 - ph[p]) * WW + w0 + w] = 0.f;
            }
        }
    }

    // ---- A staging: thread owns 8 channels of pixel (alh, apx); khalf selects channels
    const int sidx  = tid & 255;
    const int apx   = sidx & 15;
    const int alh   = sidx >> 4;          // 0..15
    const int khalf = tid >> 8;           // 0..1
    const int ah    = hq0 - 4 + alh;
    const bool av   = (ah >= 0 && ah < HH);
    const float* aptr = fr + ((size_t)b * CC + khalf * 8) * HWSZ
                           + (av ? ah : 0) * WW + (w0 + apx);

    // ---- B staging: tid<384 owns 8 channels of B pixel (bhq, bpx)
    const bool hasB = (tid < 384);
    const int bidx  = tid % 192;
    const int bkh   = (tid < 192) ? 0 : 1;
    const int bpx   = bidx % NB;
    const int bhq   = bidx / NB;
    const int wq    = w0 - RD + bpx;
    const bool bv   = hasB && (wq >= 0 && wq < WW);
    const float* bptr = fq + ((size_t)b * CC + bkh * 8) * HWSZ
                           + (hq0 + bhq) * WW + (bv ? wq : 0);

    // ---- compute role: warp pair per hq; half picks dyt range
    const int hq   = wid >> 1;
    const int half = wid & 1;
    const int ndyt = 5 - half;            // half0: dyt 0..4, half1: dyt 5..8

    float anrm = 0.f, bnrm = 0.f;
    float cAcc[15][4];
    #pragma unroll
    for (int i = 0; i < 15; ++i)
        #pragma unroll
        for (int j = 0; j < 4; ++j) cAcc[i][j] = 0.f;

    u32 ar[8], br[8];

    #define LDGSTAGE(S) do {                                                 \
        const size_t coff = (size_t)(S) * KC * HWSZ;                         \
        _Pragma("unroll")                                                    \
        for (int kc = 0; kc < 8; ++kc) {                                     \
            float v = 0.f;                                                   \
            if (av) v = aptr[coff + (size_t)kc * HWSZ];                      \
            anrm = fmaf(v, v, anrm);                                         \
            ar[kc] = cvt_tf32(v);                                            \
        }                                                                    \
        if (hasB) {                                                          \
            _Pragma("unroll")                                                \
            for (int kc = 0; kc < 8; ++kc) {                                 \
                float v = 0.f;                                               \
                if (bv) v = bptr[coff + (size_t)kc * HWSZ];                  \
                bnrm = fmaf(v, v, bnrm);                                     \
                br[kc] = cvt_tf32(v);                                        \
            }                                                                \
        }                                                                    \
    } while (0)

    #define STSSTAGE(BUF) do {                                               \
        uint4* pa = (uint4*)(sm + (BUF) * SA_STG                             \
                             + (alh * 16 + apx) * APITCH + khalf * 8);       \
        pa[0] = make_uint4(ar[0], ar[1], ar[2], ar[3]);                      \
        pa[1] = make_uint4(ar[4], ar[5], ar[6], ar[7]);                      \
        if (hasB) {                                                          \
            uint4* pb = (uint4*)(sm + SB_OFF + (BUF) * SB_STG                \
                                 + (bhq * NB + bpx) * BPITCH + bkh * 8);     \
            pb[0] = make_uint4(br[0], br[1], br[2], br[3]);                  \
            pb[1] = make_uint4(br[4], br[5], br[6], br[7]);                  \
        }                                                                    \
    } while (0)

    #define KSTEP(BUF, KS) do {                                              \
        u32 bF[3][2];                                                        \
        _Pragma("unroll")                                                    \
        for (int nt = 0; nt < 3; ++nt) {                                     \
            unsigned bd = smem_u32(sm + SB_OFF + (BUF) * SB_STG              \
                + (hq * NB + nt * 8 + (lane & 7)) * BPITCH                   \
                + (KS) * 8 + (((lane >> 3) & 1) << 2));                      \
            ldm_x2(bF[nt], bd);                                              \
        }                                                                    \
        _Pragma("unroll")                                                    \
        for (int t = 0; t < 5; ++t) {                                        \
            if (t < ndyt) {                                                  \
                const int dyt = half * 5 + t;                                \
                const int lh = hq + 8 - dyt;                                 \
                u32 aF[4];                                                   \
                unsigned ad = smem_u32(sm + (BUF) * SA_STG                   \
                    + (lh * 16 + (lane & 15)) * APITCH                       \
                    + (KS) * 8 + ((lane >> 4) << 2));                        \
                ldm_x4(aF, ad);                                              \
                mma_tf32(cAcc[t * 3 + 0], aF, bF[0]);                        \
                mma_tf32(cAcc[t * 3 + 1], aF, bF[1]);                        \
                mma_tf32(cAcc[t * 3 + 2], aF, bF[2]);                        \
            }                                                                \
        }                                                                    \
    } while (0)

    // ---- pipeline
    LDGSTAGE(0);
    STSSTAGE(0);
    __syncthreads();

    #pragma unroll 1
    for (int s = 0; s < NSTG; ++s) {
        const int buf = s & 1;
        if (s + 1 < NSTG) LDGSTAGE(s + 1);
        KSTEP(buf, 0);
        KSTEP(buf, 1);
        if (s + 1 < NSTG) STSSTAGE(buf ^ 1);
        __syncthreads();
    }

    // ---- combine norm partials
    sm[S_AN + tid] = anrm;                 // tid == khalf*256 + sidx
    if (hasB) sm[S_BN + tid] = bnrm;       // tid == bkh*192 + bidx
    __syncthreads();
    if (tid < 256) {
        sm[S_IVA + tid] = 1.0f / fmaxf(sqrtf(sm[S_AN + tid] + sm[S_AN + tid + 256]), 1e-12f);
    } else if (tid < 448) {
        const int p = tid - 256;
        sm[S_IVB + p] = 1.0f / fmaxf(sqrtf(sm[S_BN + p] + sm[S_BN + p + 192]), 1e-12f);
    }
    __syncthreads();

    // ---- epilogue
    const float scale = 1.0f / (float)CC;
    const int r1 = lane >> 2;
    const int colb = 2 * (lane & 3);

    #pragma unroll
    for (int t = 0; t < 5; ++t) {
        if (t >= ndyt) break;
        const int dyt = half * 5 + t;
        const int h = hq0 + hq + 4 - dyt;
        if (h < 0 || h >= HH) continue;
        const int lh = hq + 8 - dyt;
        const float ia1 = sm[S_IVA + lh * 16 + r1] * scale;
        const float ia2 = sm[S_IVA + lh * 16 + r1 + 8] * scale;
        #pragma unroll
        for (int nt = 0; nt < 3; ++nt) {
            const int col0 = nt * 8 + colb;
            const float ib0 = sm[S_IVB + hq * NB + col0];
            const float ib1 = sm[S_IVB + hq * NB + col0 + 1];
            const float* cf = cAcc[t * 3 + nt];
            size_t pbase = ((size_t)b * 81 + dyt * ND) * HWSZ + h * WW + w0;
            int dx;
            dx = col0 - r1;
            if (dx >= 0 && dx < ND) out[pbase + (size_t)dx * HWSZ + r1] = cf[0] * ia1 * ib0;
            dx = col0 + 1 - r1;
            if (dx >= 0 && dx < ND) out[pbase + (size_t)dx * HWSZ + r1] = cf[1] * ia1 * ib1;
            dx = col0 - (r1 + 8);
            if (dx >= 0 && dx < ND) out[pbase + (size_t)dx * HWSZ + r1 + 8] = cf[2] * ia2 * ib0;
            dx = col0 + 1 - (r1 + 8);
            if (dx >= 0 && dx < ND) out[pbase + (size_t)dx * HWSZ + r1 + 8] = cf[3] * ia2 * ib1;
        }
    }
    #undef LDGSTAGE
    #undef STSSTAGE
    #undef KSTEP
}

extern "C" void kernel_launch(void* const* d_in, const int* in_sizes, int n_in,
                              void* d_out, int out_size) {
    const float* fr = (const float*)d_in[0];
    const float* fq = (const float*)d_in[1];
    float* out = (float*)d_out;
    (void)in_sizes; (void)n_in; (void)out_size;

    cudaFuncSetAttribute(corr_mma_kernel,
                         cudaFuncAttributeMaxDynamicSharedMemorySize, SMEM_BYTES);

    dim3 grid(WW / WT, HH / HQB, BB);   // (8, 12, 8) = 768 CTAs
    corr_mma_kernel<<<grid, NTHREADS, SMEM_BYTES>>>(fr, fq, out);
}

// round 14
// speedup vs baseline: 1.3170x; 1.3170x over previous
#include <cuda_runtime.h>
#include <cstdint>
#include <math.h>

#define BB 8
#define CC 256
#define HH 96
#define WW 128
#define HWSZ (HH*WW)
#define RD 4
#define ND 9

#define HQB 8
#define WT 16
#define NB 24
#define KC 16
#define NSTG (CC/KC)
#define APITCH 20
#define BPITCH 20
#define NTHREADS 256

#define SA_STG (16*16*APITCH)
#define SB_OFF (2*SA_STG)
#define SB_STG (HQB*NB*BPITCH)
#define SINVA_OFF (SB_OFF + 2*SB_STG)
#define SINVB_OFF (SINVA_OFF + 256)
#define SMEM_FLOATS (SINVB_OFF + HQB*NB)
#define SMEM_BYTES (SMEM_FLOATS*4)

typedef unsigned int u32;

__device__ __forceinline__ unsigned smem_u32(const void* p) {
    return (unsigned)__cvta_generic_to_shared(p);
}
__device__ __forceinline__ u32 cvt_tf32(float v) {
    u32 r; asm("cvt.rna.tf32.f32 %0, %1;" : "=r"(r) : "f"(v)); return r;
}
__device__ __forceinline__ void mma_tf32(float c[4], const u32 a[4], const u32 b[2]) {
    asm volatile(
        "mma.sync.aligned.m16n8k8.row.col.f32.tf32.tf32.f32 "
        "{%0,%1,%2,%3}, {%4,%5,%6,%7}, {%8,%9}, {%0,%1,%2,%3};"
        : "+f"(c[0]), "+f"(c[1]), "+f"(c[2]), "+f"(c[3])
        : "r"(a[0]), "r"(a[1]), "r"(a[2]), "r"(a[3]), "r"(b[0]), "r"(b[1]));
}
__device__ __forceinline__ void ldm_x4(u32 r[4], unsigned addr) {
    asm volatile("ldmatrix.sync.aligned.m8n8.x4.shared.b16 {%0,%1,%2,%3}, [%4];"
                 : "=r"(r[0]), "=r"(r[1]), "=r"(r[2]), "=r"(r[3]) : "r"(addr));
}
__device__ __forceinline__ void ldm_x2(u32 r[2], unsigned addr) {
    asm volatile("ldmatrix.sync.aligned.m8n8.x2.shared.b16 {%0,%1}, [%2];"
                 : "=r"(r[0]), "=r"(r[1]) : "r"(addr));
}

__global__ __launch_bounds__(NTHREADS, 1)
void corr_mma_kernel(const float* __restrict__ fr, const float* __restrict__ fq,
                     float* __restrict__ out) {
    extern __shared__ float sm[];
    const int tid  = threadIdx.x;
    const int wid  = tid >> 5;
    const int lane = tid & 31;

    const int b   = blockIdx.z;
    const int hq0 = blockIdx.y * HQB;
    const int w0  = blockIdx.x * WT;

    // ---- structural-zero outputs (OOB fq rows): written by edge CTAs only
    {
        const int pd[10] = {0,0,0,0,1,1,1,2,2,3};
        const int ph[10] = {0,1,2,3,0,1,2,0,1,0};
        if (blockIdx.y == 0) {
            for (int idx = tid; idx < 1440; idx += NTHREADS) {
                int p = idx / 144, rem = idx % 144, dx = rem / 16, w = rem % 16;
                out[((size_t)b * 81 + pd[p] * ND + dx) * HWSZ + ph[p] * WW + w0 + w] = 0.f;
            }
        }
        if (blockIdx.y == (HH / HQB) - 1) {
            for (int idx = tid; idx < 1440; idx += NTHREADS) {
                int p = idx / 144, rem = idx % 144, dx = rem / 16, w = rem % 16;
                out[((size_t)b * 81 + (8 - pd[p]) * ND + dx) * HWSZ
                    + (HH - 1 - ph[p]) * WW + w0 + w] = 0.f;
            }
        }
    }

    // ---- A staging role
    const int apx = tid & 15;
    const int alh = tid >> 4;
    const int ah  = hq0 - 4 + alh;
    const bool av = (ah >= 0 && ah < HH);
    const float* aptr = fr + (size_t)b * CC * HWSZ + (av ? ah : 0) * WW + (w0 + apx);

    // ---- B staging role
    const int bpx = (tid < 192) ? (tid % NB) : 0;
    const int bhq = (tid < 192) ? (tid / NB) : 0;
    const int wq  = w0 - RD + bpx;
    const bool bv = (tid < 192) && (wq >= 0 && wq < WW);
    const float* bptr = fq + (size_t)b * CC * HWSZ + (hq0 + bhq) * WW + (bv ? wq : 0);

    float anrm = 0.f, bnrm = 0.f;
    float cAcc[27][4];
    #pragma unroll
    for (int i = 0; i < 27; ++i)
        #pragma unroll
        for (int j = 0; j < 4; ++j) cAcc[i][j] = 0.f;

    // raw staged values (decoupled from cvt/norm)
    float avr[KC], bvr[KC];

    // pure load batch -- no consumers, full MLP
    #define LDGSTAGE(S) do {                                                 \
        const size_t coff = (size_t)(S) * KC * HWSZ;                         \
        _Pragma("unroll")                                                    \
        for (int kc = 0; kc < KC; ++kc)                                      \
            avr[kc] = av ? aptr[coff + (size_t)kc * HWSZ] : 0.f;             \
        _Pragma("unroll")                                                    \
        for (int kc = 0; kc < KC; ++kc)                                      \
            bvr[kc] = bv ? bptr[coff + (size_t)kc * HWSZ] : 0.f;             \
    } while (0)

    // norm accumulation + cvt + store at stage end (loads have landed by now)
    #define STSSTAGE(BUF) do {                                               \
        _Pragma("unroll")                                                    \
        for (int kc = 0; kc < KC; ++kc) anrm = fmaf(avr[kc], avr[kc], anrm); \
        uint4* pa = (uint4*)(sm + (BUF) * SA_STG + (alh * 16 + apx) * APITCH);\
        pa[0] = make_uint4(cvt_tf32(avr[0]), cvt_tf32(avr[1]),               \
                           cvt_tf32(avr[2]), cvt_tf32(avr[3]));              \
        pa[1] = make_uint4(cvt_tf32(avr[4]), cvt_tf32(avr[5]),               \
                           cvt_tf32(avr[6]), cvt_tf32(avr[7]));              \
        pa[2] = make_uint4(cvt_tf32(avr[8]), cvt_tf32(avr[9]),               \
                           cvt_tf32(avr[10]), cvt_tf32(avr[11]));            \
        pa[3] = make_uint4(cvt_tf32(avr[12]), cvt_tf32(avr[13]),             \
                           cvt_tf32(avr[14]), cvt_tf32(avr[15]));            \
        if (tid < 192) {                                                     \
            _Pragma("unroll")                                                \
            for (int kc = 0; kc < KC; ++kc)                                  \
                bnrm = fmaf(bvr[kc], bvr[kc], bnrm);                         \
            uint4* pb = (uint4*)(sm + SB_OFF + (BUF) * SB_STG                \
                                 + (bhq * NB + bpx) * BPITCH);               \
            pb[0] = make_uint4(cvt_tf32(bvr[0]), cvt_tf32(bvr[1]),           \
                               cvt_tf32(bvr[2]), cvt_tf32(bvr[3]));          \
            pb[1] = make_uint4(cvt_tf32(bvr[4]), cvt_tf32(bvr[5]),           \
                               cvt_tf32(bvr[6]), cvt_tf32(bvr[7]));          \
            pb[2] = make_uint4(cvt_tf32(bvr[8]), cvt_tf32(bvr[9]),           \
                               cvt_tf32(bvr[10]), cvt_tf32(bvr[11]));        \
            pb[3] = make_uint4(cvt_tf32(bvr[12]), cvt_tf32(bvr[13]),         \
                               cvt_tf32(bvr[14]), cvt_tf32(bvr[15]));        \
        }                                                                    \
    } while (0)

    #define KSTEP(BUF, KS) do {                                              \
        u32 bF[3][2];                                                        \
        _Pragma("unroll")                                                    \
        for (int nt = 0; nt < 3; ++nt) {                                     \
            unsigned bd = smem_u32(sm + SB_OFF + (BUF) * SB_STG              \
                + (wid * NB + nt * 8 + (lane & 7)) * BPITCH                  \
                + (KS) * 8 + (((lane >> 3) & 1) << 2));                      \
            ldm_x2(bF[nt], bd);                                              \
        }                                                                    \
        _Pragma("unroll")                                                    \
        for (int dyt = 0; dyt < 9; ++dyt) {                                  \
            const int lh = wid + 8 - dyt;                                    \
            u32 aF[4];                                                       \
            unsigned ad = smem_u32(sm + (BUF) * SA_STG                       \
                + (lh * 16 + (lane & 15)) * APITCH                           \
                + (KS) * 8 + ((lane >> 4) << 2));                            \
            ldm_x4(aF, ad);                                                  \
            mma_tf32(cAcc[dyt * 3 + 0], aF, bF[0]);                          \
            mma_tf32(cAcc[dyt * 3 + 1], aF, bF[1]);                          \
            mma_tf32(cAcc[dyt * 3 + 2], aF, bF[2]);                          \
        }                                                                    \
    } while (0)

    LDGSTAGE(0);
    STSSTAGE(0);
    __syncthreads();

    #pragma unroll 1
    for (int s = 0; s < NSTG; ++s) {
        const int buf = s & 1;
        if (s + 1 < NSTG) LDGSTAGE(s + 1);
        KSTEP(buf, 0);
        KSTEP(buf, 1);
        if (s + 1 < NSTG) STSSTAGE(buf ^ 1);
        __syncthreads();
    }

    // ---- norms to smem
    sm[SINVA_OFF + alh * 16 + apx] = 1.0f / fmaxf(sqrtf(anrm), 1e-12f);
    if (tid < 192)
        sm[SINVB_OFF + bhq * NB + bpx] = 1.0f / fmaxf(sqrtf(bnrm), 1e-12f);
    __syncthreads();

    // ---- epilogue
    const float scale = 1.0f / (float)CC;
    const int r1 = lane >> 2;
    const int colb = 2 * (lane & 3);

    #pragma unroll
    for (int dyt = 0; dyt < 9; ++dyt) {
        const int h = hq0 + wid + 4 - dyt;
        if (h < 0 || h >= HH) continue;
        const int lh = wid + 8 - dyt;
        const float ia1 = sm[SINVA_OFF + lh * 16 + r1] * scale;
        const float ia2 = sm[SINVA_OFF + lh * 16 + r1 + 8] * scale;
        #pragma unroll
        for (int nt = 0; nt < 3; ++nt) {
            const int col0 = nt * 8 + colb;
            const float ib0 = sm[SINVB_OFF + wid * NB + col0];
            const float ib1 = sm[SINVB_OFF + wid * NB + col0 + 1];
            const float* cf = cAcc[dyt * 3 + nt];
            int dx;
            size_t pbase = ((size_t)b * 81 + dyt * ND) * HWSZ + h * WW + w0;
            dx = col0 - r1;
            if (dx >= 0 && dx < ND) out[pbase + (size_t)dx * HWSZ + r1] = cf[0] * ia1 * ib0;
            dx = col0 + 1 - r1;
            if (dx >= 0 && dx < ND) out[pbase + (size_t)dx * HWSZ + r1] = cf[1] * ia1 * ib1;
            dx = col0 - (r1 + 8);
            if (dx >= 0 && dx < ND) out[pbase + (size_t)dx * HWSZ + r1 + 8] = cf[2] * ia2 * ib0;
            dx = col0 + 1 - (r1 + 8);
            if (dx >= 0 && dx < ND) out[pbase + (size_t)dx * HWSZ + r1 + 8] = cf[3] * ia2 * ib1;
        }
    }
    #undef LDGSTAGE
    #undef STSSTAGE
    #undef KSTEP
}

extern "C" void kernel_launch(void* const* d_in, const int* in_sizes, int n_in,
                              void* d_out, int out_size) {
    const float* fr = (const float*)d_in[0];
    const float* fq = (const float*)d_in[1];
    float* out = (float*)d_out;
    (void)in_sizes; (void)n_in; (void)out_size;

    cudaFuncSetAttribute(corr_mma_kernel,
                         cudaFuncAttributeMaxDynamicSharedMemorySize, SMEM_BYTES);

    dim3 grid(WW / WT, HH / HQB, BB);   // (8, 12, 8) = 768 CTAs
    corr_mma_kernel<<<grid, NTHREADS, SMEM_BYTES>>>(fr, fq, out);
}